// round 2
// baseline (speedup 1.0000x reference)
#include <cuda_runtime.h>
#include <cuda_bf16.h>

#define N_NODES 100000
#define MAX_NNZ 3200000
#define SCAN_BS 512
#define NBLK ((N_NODES + SCAN_BS - 1) / SCAN_BS)   // 196

// Scratch (no cudaMalloc allowed) — ~232 MB total.
__device__ float g_buf0[(size_t)N_NODES * 256];
__device__ float g_buf1[(size_t)N_NODES * 256];
__device__ int   g_count[N_NODES];
__device__ int   g_rowptr[N_NODES + 1];
__device__ int   g_wptr[N_NODES];
__device__ int   g_blocksum[NBLK];
__device__ int   g_ecol[MAX_NNZ];
__device__ float g_eval[MAX_NNZ];

// ---------------------------------------------------------------------------
// CSR build: histogram -> scan -> scatter  (per-launch, graph-capturable)
// ---------------------------------------------------------------------------
__global__ void zero_counts_kernel() {
    int i = blockIdx.x * blockDim.x + threadIdx.x;
    if (i < N_NODES) g_count[i] = 0;
}

__global__ void hist_kernel(const int* __restrict__ rows, int nnz) {
    int i = blockIdx.x * blockDim.x + threadIdx.x;
    if (i < nnz) atomicAdd(&g_count[rows[i]], 1);
}

__global__ void scan1_kernel() {
    __shared__ int s[SCAN_BS];
    int tid = threadIdx.x;
    int i = blockIdx.x * SCAN_BS + tid;
    int v = (i < N_NODES) ? g_count[i] : 0;
    s[tid] = v;
    __syncthreads();
#pragma unroll
    for (int off = 1; off < SCAN_BS; off <<= 1) {
        int t = (tid >= off) ? s[tid - off] : 0;
        __syncthreads();
        s[tid] += t;
        __syncthreads();
    }
    if (i < N_NODES) g_rowptr[i] = s[tid] - v;           // local exclusive
    if (tid == SCAN_BS - 1) g_blocksum[blockIdx.x] = s[tid];
}

__global__ void scan2_kernel() {
    if (threadIdx.x == 0 && blockIdx.x == 0) {
        int acc = 0;
        for (int b = 0; b < NBLK; b++) {
            int t = g_blocksum[b];
            g_blocksum[b] = acc;
            acc += t;
        }
    }
}

__global__ void scan3_kernel(int nnz) {
    int i = blockIdx.x * blockDim.x + threadIdx.x;
    if (i < N_NODES) {
        int rp = g_rowptr[i] + g_blocksum[i / SCAN_BS];
        g_rowptr[i] = rp;
        g_wptr[i]   = rp;
    }
    if (i == 0) g_rowptr[N_NODES] = nnz;
}

__global__ void scatter_kernel(const int* __restrict__ rows,
                               const int* __restrict__ cols,
                               const float* __restrict__ vals, int nnz) {
    int i = blockIdx.x * blockDim.x + threadIdx.x;
    if (i >= nnz) return;
    int r = rows[i];
    int pos = atomicAdd(&g_wptr[r], 1);
    g_ecol[pos] = cols[i];
    g_eval[pos] = vals[i];
}

// ---------------------------------------------------------------------------
// Gather SpMM: out[r, foff:foff+128] = sum_e vals[e] * h[col[e], foff:foff+128]
// One warp per row; lane owns 4 consecutive floats; register accumulation;
// zero atomics; output written exactly once.
// ---------------------------------------------------------------------------
__global__ void spmm_csr_kernel(const float* __restrict__ h,
                                float* __restrict__ out,
                                int d, int foff) {
    int r = (blockIdx.x * blockDim.x + threadIdx.x) >> 5;
    if (r >= N_NODES) return;
    int lane = threadIdx.x & 31;

    int beg = __ldg(&g_rowptr[r]);
    int end = __ldg(&g_rowptr[r + 1]);

    float4 acc = make_float4(0.f, 0.f, 0.f, 0.f);

    int e = beg;
    // unrolled-by-2 for MLP on the dependent (ecol -> h) chain
    for (; e + 1 < end; e += 2) {
        int   c0 = __ldg(g_ecol + e);
        int   c1 = __ldg(g_ecol + e + 1);
        float v0 = __ldg(g_eval + e);
        float v1 = __ldg(g_eval + e + 1);
        float4 h0 = __ldg(reinterpret_cast<const float4*>(h + (size_t)c0 * d + foff) + lane);
        float4 h1 = __ldg(reinterpret_cast<const float4*>(h + (size_t)c1 * d + foff) + lane);
        acc.x = fmaf(v0, h0.x, acc.x); acc.y = fmaf(v0, h0.y, acc.y);
        acc.z = fmaf(v0, h0.z, acc.z); acc.w = fmaf(v0, h0.w, acc.w);
        acc.x = fmaf(v1, h1.x, acc.x); acc.y = fmaf(v1, h1.y, acc.y);
        acc.z = fmaf(v1, h1.z, acc.z); acc.w = fmaf(v1, h1.w, acc.w);
    }
    if (e < end) {
        int   c0 = __ldg(g_ecol + e);
        float v0 = __ldg(g_eval + e);
        float4 h0 = __ldg(reinterpret_cast<const float4*>(h + (size_t)c0 * d + foff) + lane);
        acc.x = fmaf(v0, h0.x, acc.x); acc.y = fmaf(v0, h0.y, acc.y);
        acc.z = fmaf(v0, h0.z, acc.z); acc.w = fmaf(v0, h0.w, acc.w);
    }

    *(reinterpret_cast<float4*>(out + (size_t)r * d + foff) + lane) = acc;
}

// ---------------------------------------------------------------------------
// GEMM: C[n,j] = sum_k A[n,k] * W[j,k]  (A:[N,K] row-major, W:[J,K] row-major)
// 64x64 tile, BK=16, 256 threads, 4x4 micro-tile, optional ReLU.
// ---------------------------------------------------------------------------
template <int K, bool RELU>
__global__ void gemm_kernel(const float* __restrict__ A,
                            const float* __restrict__ W,
                            float* __restrict__ C,
                            int N, int J) {
    __shared__ __align__(16) float As[16][68];
    __shared__ __align__(16) float Ws[16][68];

    const int tid = threadIdx.x;
    const int tx  = tid & 15;
    const int ty  = tid >> 4;
    const int rowBase = blockIdx.x * 64;
    const int colBase = blockIdx.y * 64;

    const int lr = tid >> 2;
    const int lk = (tid & 3) * 4;

    float acc[4][4];
#pragma unroll
    for (int i = 0; i < 4; i++)
#pragma unroll
        for (int j = 0; j < 4; j++) acc[i][j] = 0.f;

    for (int k0 = 0; k0 < K; k0 += 16) {
        int arow = rowBase + lr;
        float4 av = make_float4(0.f, 0.f, 0.f, 0.f);
        if (arow < N)
            av = *reinterpret_cast<const float4*>(A + (size_t)arow * K + k0 + lk);
        As[lk + 0][lr] = av.x; As[lk + 1][lr] = av.y;
        As[lk + 2][lr] = av.z; As[lk + 3][lr] = av.w;

        int wrow = colBase + lr;   // J is a multiple of 64
        float4 wv = *reinterpret_cast<const float4*>(W + (size_t)wrow * K + k0 + lk);
        Ws[lk + 0][lr] = wv.x; Ws[lk + 1][lr] = wv.y;
        Ws[lk + 2][lr] = wv.z; Ws[lk + 3][lr] = wv.w;

        __syncthreads();

#pragma unroll
        for (int kk = 0; kk < 16; kk++) {
            float4 a4 = *reinterpret_cast<const float4*>(&As[kk][ty * 4]);
            float4 b4 = *reinterpret_cast<const float4*>(&Ws[kk][tx * 4]);
            float a[4] = {a4.x, a4.y, a4.z, a4.w};
            float b[4] = {b4.x, b4.y, b4.z, b4.w};
#pragma unroll
            for (int i = 0; i < 4; i++)
#pragma unroll
                for (int j = 0; j < 4; j++)
                    acc[i][j] = fmaf(a[i], b[j], acc[i][j]);
        }
        __syncthreads();
    }

#pragma unroll
    for (int i = 0; i < 4; i++) {
        int r = rowBase + ty * 4 + i;
        if (r >= N) continue;
#pragma unroll
        for (int j = 0; j < 4; j++) {
            int cc = colBase + tx * 4 + j;
            float v = acc[i][j];
            if (RELU) v = fmaxf(v, 0.f);
            C[(size_t)r * J + cc] = v;
        }
    }
}

// ---------------------------------------------------------------------------
// Sequence: CSR build, then
//   h1 = A@x; h2 = A@h1; h3 = relu(h2 @ W1^T);
//   h4 = A@h3; h5 = A@h4; out = h5 @ W2^T
// ---------------------------------------------------------------------------
extern "C" void kernel_launch(void* const* d_in, const int* in_sizes, int n_in,
                              void* d_out, int out_size) {
    const float* x    = (const float*)d_in[0];
    const int*   rows = (const int*)  d_in[1];
    const int*   cols = (const int*)  d_in[2];
    const float* vals = (const float*)d_in[3];
    const float* W1   = (const float*)d_in[4];
    const float* W2   = (const float*)d_in[5];
    float* out = (float*)d_out;

    const int nnz = in_sizes[1];
    const int N   = N_NODES;

    float *buf0, *buf1;
    cudaGetSymbolAddress((void**)&buf0, g_buf0);
    cudaGetSymbolAddress((void**)&buf1, g_buf1);

    const int BT = 256;
    const int nodeBlocks = (N + BT - 1) / BT;
    const int nnzBlocks  = (nnz + BT - 1) / BT;
    const int spmmBlocks = (N * 32 + BT - 1) / BT;

    // ---- CSR build
    zero_counts_kernel<<<nodeBlocks, BT>>>();
    hist_kernel<<<nnzBlocks, BT>>>(rows, nnz);
    scan1_kernel<<<NBLK, SCAN_BS>>>();
    scan2_kernel<<<1, 32>>>();
    scan3_kernel<<<nodeBlocks, BT>>>(nnz);
    scatter_kernel<<<nnzBlocks, BT>>>(rows, cols, vals, nnz);

    // ---- layer 1, propagate x2 (d=128)
    spmm_csr_kernel<<<spmmBlocks, BT>>>(x,    buf0, 128, 0);
    spmm_csr_kernel<<<spmmBlocks, BT>>>(buf0, buf1, 128, 0);

    // ---- layer 1 linear + relu: buf0 = relu(buf1 @ W1^T)  [N,256]
    {
        dim3 grid((N + 63) / 64, 256 / 64);
        gemm_kernel<128, true><<<grid, 256>>>(buf1, W1, buf0, N, 256);
    }

    // ---- layer 2, propagate x2 (d=256, two feature passes each for L2 residency)
    spmm_csr_kernel<<<spmmBlocks, BT>>>(buf0, buf1, 256, 0);
    spmm_csr_kernel<<<spmmBlocks, BT>>>(buf0, buf1, 256, 128);
    spmm_csr_kernel<<<spmmBlocks, BT>>>(buf1, buf0, 256, 0);
    spmm_csr_kernel<<<spmmBlocks, BT>>>(buf1, buf0, 256, 128);

    // ---- layer 2 linear: out = buf0 @ W2^T  [N,128]
    {
        dim3 grid((N + 63) / 64, 128 / 64);
        gemm_kernel<256, false><<<grid, 256>>>(buf0, W2, out, N, 128);
    }
}

// round 5
// speedup vs baseline: 2.2183x; 2.2183x over previous
#include <cuda_runtime.h>
#include <cuda_fp16.h>
#include <cuda_bf16.h>

#define N_NODES 100000
#define MAX_NNZ 3200000
#define SCAN_BS 512
#define NBLK ((N_NODES + SCAN_BS - 1) / SCAN_BS)   // 196

// Exact power-of-2 scaling for the post-W2 stages (keeps t in fp16-normal range)
#define GSCALE     1024.0f
#define GSCALE_INV (1.0f / 1024.0f)

// ---------------- scratch (no cudaMalloc allowed) ----------------
__device__ __half g_xh [(size_t)N_NODES * 128];  // x in fp16
__device__ __half g_ha [(size_t)N_NODES * 128];  // h1 / g' / ...
__device__ __half g_hb [(size_t)N_NODES * 128];  // h2 / t'
__device__ __half g_h3 [(size_t)N_NODES * 256];  // h3
__device__ __half g_w1h[256 * 128];
__device__ __half g_w2h[128 * 256];
__device__ int    g_count[N_NODES];
__device__ int    g_rowptr[N_NODES + 1];
__device__ int    g_wptr[N_NODES];
__device__ int    g_blocksum[NBLK];
__device__ int    g_ecol[MAX_NNZ];
__device__ float  g_eval[MAX_NNZ];

// ---------------------------------------------------------------------------
// CSR build: histogram -> scan -> scatter  (per-replay, graph-capturable)
// ---------------------------------------------------------------------------
__global__ void zero_counts_kernel() {
    int i = blockIdx.x * blockDim.x + threadIdx.x;
    if (i < N_NODES) g_count[i] = 0;
}

__global__ void hist_kernel(const int* __restrict__ rows, int nnz) {
    int i = blockIdx.x * blockDim.x + threadIdx.x;
    if (i < nnz) atomicAdd(&g_count[rows[i]], 1);
}

__global__ void scan1_kernel() {
    __shared__ int s[SCAN_BS];
    int tid = threadIdx.x;
    int i = blockIdx.x * SCAN_BS + tid;
    int v = (i < N_NODES) ? g_count[i] : 0;
    s[tid] = v;
    __syncthreads();
#pragma unroll
    for (int off = 1; off < SCAN_BS; off <<= 1) {
        int t = (tid >= off) ? s[tid - off] : 0;
        __syncthreads();
        s[tid] += t;
        __syncthreads();
    }
    if (i < N_NODES) g_rowptr[i] = s[tid] - v;
    if (tid == SCAN_BS - 1) g_blocksum[blockIdx.x] = s[tid];
}

__global__ void scan2_kernel() {
    if (threadIdx.x == 0 && blockIdx.x == 0) {
        int acc = 0;
        for (int b = 0; b < NBLK; b++) {
            int t = g_blocksum[b];
            g_blocksum[b] = acc;
            acc += t;
        }
    }
}

__global__ void scan3_kernel(int nnz) {
    int i = blockIdx.x * blockDim.x + threadIdx.x;
    if (i < N_NODES) {
        int rp = g_rowptr[i] + g_blocksum[i / SCAN_BS];
        g_rowptr[i] = rp;
        g_wptr[i]   = rp;
    }
    if (i == 0) g_rowptr[N_NODES] = nnz;
}

__global__ void scatter_kernel(const int* __restrict__ rows,
                               const int* __restrict__ cols,
                               const float* __restrict__ vals, int nnz) {
    int i = blockIdx.x * blockDim.x + threadIdx.x;
    if (i >= nnz) return;
    int r = rows[i];
    int pos = atomicAdd(&g_wptr[r], 1);
    g_ecol[pos] = cols[i];
    g_eval[pos] = vals[i];
}

// ---------------------------------------------------------------------------
// fp32 -> fp16 conversion
// ---------------------------------------------------------------------------
__global__ void f2h_kernel(const float* __restrict__ src, __half* __restrict__ dst, int n) {
    int i = blockIdx.x * blockDim.x + threadIdx.x;
    if (i < n) dst[i] = __float2half_rn(src[i]);
}

// ---------------------------------------------------------------------------
// Gather SpMM (d=128): one warp per row, lane owns 4 features, fp32 accum.
// Input always fp16. Output fp16 (scaled by oscale) or fp32 (scaled).
// ---------------------------------------------------------------------------
__device__ __forceinline__ void acc_half_row(const __half* __restrict__ h, int c,
                                             int lane, float v, float4& acc) {
    uint2 u = __ldg(reinterpret_cast<const uint2*>(h + (size_t)c * 128) + lane);
    __half2 p0 = *reinterpret_cast<__half2*>(&u.x);
    __half2 p1 = *reinterpret_cast<__half2*>(&u.y);
    float2 f0 = __half22float2(p0);
    float2 f1 = __half22float2(p1);
    acc.x = fmaf(v, f0.x, acc.x); acc.y = fmaf(v, f0.y, acc.y);
    acc.z = fmaf(v, f1.x, acc.z); acc.w = fmaf(v, f1.y, acc.w);
}

template <bool OUT_HALF>
__global__ void spmm_h_kernel(const __half* __restrict__ h, void* __restrict__ outv,
                              float oscale) {
    int r = (blockIdx.x * blockDim.x + threadIdx.x) >> 5;
    if (r >= N_NODES) return;
    int lane = threadIdx.x & 31;

    int beg = __ldg(&g_rowptr[r]);
    int end = __ldg(&g_rowptr[r + 1]);

    float4 acc = make_float4(0.f, 0.f, 0.f, 0.f);
    int e = beg;
    for (; e + 3 < end; e += 4) {
        int   c0 = __ldg(g_ecol + e);
        int   c1 = __ldg(g_ecol + e + 1);
        int   c2 = __ldg(g_ecol + e + 2);
        int   c3 = __ldg(g_ecol + e + 3);
        float v0 = __ldg(g_eval + e);
        float v1 = __ldg(g_eval + e + 1);
        float v2 = __ldg(g_eval + e + 2);
        float v3 = __ldg(g_eval + e + 3);
        acc_half_row(h, c0, lane, v0, acc);
        acc_half_row(h, c1, lane, v1, acc);
        acc_half_row(h, c2, lane, v2, acc);
        acc_half_row(h, c3, lane, v3, acc);
    }
    for (; e < end; e++) {
        acc_half_row(h, __ldg(g_ecol + e), lane, __ldg(g_eval + e), acc);
    }

    acc.x *= oscale; acc.y *= oscale; acc.z *= oscale; acc.w *= oscale;

    if (OUT_HALF) {
        __half2 o0 = __floats2half2_rn(acc.x, acc.y);
        __half2 o1 = __floats2half2_rn(acc.z, acc.w);
        uint2 u;
        u.x = *reinterpret_cast<unsigned*>(&o0);
        u.y = *reinterpret_cast<unsigned*>(&o1);
        *(reinterpret_cast<uint2*>((__half*)outv + (size_t)r * 128) + lane) = u;
    } else {
        *(reinterpret_cast<float4*>((float*)outv + (size_t)r * 128) + lane) = acc;
    }
}

// ---------------------------------------------------------------------------
// Tensor-core GEMM: C[n,j] = oscale * sum_k A[n,k] * W[j,k], fp16 in, fp32
// accum, fp16 out (optional ReLU). mma.sync.m16n8k16.row.col — W[J,K]
// row-major is exactly the "col" B operand, so no transposes.
// Block: 128(M) x 64(J), 8 warps as 4(m) x 2(j); warp tile 32x32 = 2x4 mmas.
// ---------------------------------------------------------------------------
#define GT_PAD 24   // smem row stride in halves (48B): conflict-free frag loads

template <int K, bool RELU>
__global__ void gemm_tc_kernel(const __half* __restrict__ A,
                               const __half* __restrict__ W,
                               __half* __restrict__ C,
                               int N, int J, float oscale) {
    __shared__ __align__(16) __half As[128][GT_PAD];
    __shared__ __align__(16) __half Ws[64][GT_PAD];

    const int tid  = threadIdx.x;      // 0..255
    const int lane = tid & 31;
    const int wid  = tid >> 5;         // 0..7
    const int warpM = wid & 3;         // 0..3  (32 rows each)
    const int warpJ = wid >> 2;        // 0..1  (32 cols each)
    const int gid = lane >> 2;         // 0..7
    const int tig = lane & 3;          // 0..3

    const int rowBase = blockIdx.x * 128;
    const int colBase = blockIdx.y * 64;

    float acc[2][4][4];
#pragma unroll
    for (int m = 0; m < 2; m++)
#pragma unroll
        for (int n = 0; n < 4; n++)
#pragma unroll
            for (int q = 0; q < 4; q++) acc[m][n][q] = 0.f;

    const int lrow = tid >> 1;         // 0..127
    const int lseg = (tid & 1) * 8;    // 0 or 8

    for (int k0 = 0; k0 < K; k0 += 16) {
        // A tile: 128 rows x 16 halves
        {
            uint4 v = make_uint4(0, 0, 0, 0);
            int arow = rowBase + lrow;
            if (arow < N)
                v = *reinterpret_cast<const uint4*>(A + (size_t)arow * K + k0 + lseg);
            *reinterpret_cast<uint4*>(&As[lrow][lseg]) = v;
        }
        // W tile: 64 rows x 16 halves
        if (tid < 128) {
            int wrow = colBase + lrow;  // J is a multiple of 64
            uint4 v = *reinterpret_cast<const uint4*>(W + (size_t)wrow * K + k0 + lseg);
            *reinterpret_cast<uint4*>(&Ws[lrow][lseg]) = v;
        }
        __syncthreads();

        unsigned a[2][4], b[4][2];
#pragma unroll
        for (int m = 0; m < 2; m++) {
            int r0 = warpM * 32 + m * 16 + gid;
            a[m][0] = *reinterpret_cast<const unsigned*>(&As[r0    ][tig * 2    ]);
            a[m][1] = *reinterpret_cast<const unsigned*>(&As[r0 + 8][tig * 2    ]);
            a[m][2] = *reinterpret_cast<const unsigned*>(&As[r0    ][tig * 2 + 8]);
            a[m][3] = *reinterpret_cast<const unsigned*>(&As[r0 + 8][tig * 2 + 8]);
        }
#pragma unroll
        for (int n = 0; n < 4; n++) {
            int jr = warpJ * 32 + n * 8 + gid;
            b[n][0] = *reinterpret_cast<const unsigned*>(&Ws[jr][tig * 2    ]);
            b[n][1] = *reinterpret_cast<const unsigned*>(&Ws[jr][tig * 2 + 8]);
        }

#pragma unroll
        for (int m = 0; m < 2; m++)
#pragma unroll
            for (int n = 0; n < 4; n++) {
                asm volatile(
                    "mma.sync.aligned.m16n8k16.row.col.f32.f16.f16.f32 "
                    "{%0,%1,%2,%3}, {%4,%5,%6,%7}, {%8,%9}, {%0,%1,%2,%3};\n"
                    : "+f"(acc[m][n][0]), "+f"(acc[m][n][1]),
                      "+f"(acc[m][n][2]), "+f"(acc[m][n][3])
                    : "r"(a[m][0]), "r"(a[m][1]), "r"(a[m][2]), "r"(a[m][3]),
                      "r"(b[n][0]), "r"(b[n][1]));
            }
        __syncthreads();
    }

    // epilogue: c0,c1 -> row gid; c2,c3 -> row gid+8; cols tig*2, tig*2+1
#pragma unroll
    for (int m = 0; m < 2; m++) {
        int rbase = rowBase + warpM * 32 + m * 16;
#pragma unroll
        for (int n = 0; n < 4; n++) {
            int col = colBase + warpJ * 32 + n * 8 + tig * 2;
            float v0 = acc[m][n][0], v1 = acc[m][n][1];
            float v2 = acc[m][n][2], v3 = acc[m][n][3];
            if (RELU) {
                v0 = fmaxf(v0, 0.f); v1 = fmaxf(v1, 0.f);
                v2 = fmaxf(v2, 0.f); v3 = fmaxf(v3, 0.f);
            }
            v0 *= oscale; v1 *= oscale; v2 *= oscale; v3 *= oscale;
            int r0 = rbase + gid;
            int r1 = rbase + gid + 8;
            if (r0 < N) {
                __half2 p = __floats2half2_rn(v0, v1);
                *reinterpret_cast<__half2*>(C + (size_t)r0 * J + col) = p;
            }
            if (r1 < N) {
                __half2 p = __floats2half2_rn(v2, v3);
                *reinterpret_cast<__half2*>(C + (size_t)r1 * J + col) = p;
            }
        }
    }
}

// ---------------------------------------------------------------------------
// Sequence (W2 folded early; all propagates d=128 fp16; scale trick keeps
// post-W2 magnitudes in fp16-normal range, removed exactly at the end):
//   h1 = A@xh; h2 = A@h1
//   h3 = relu(h2 @ W1^T)           [N,256] fp16
//   g' = 1024 * (h3 @ W2^T)        [N,128] fp16
//   t' = A@g'                      [N,128] fp16
//   out = (A@t') / 1024            [N,128] fp32
// ---------------------------------------------------------------------------
extern "C" void kernel_launch(void* const* d_in, const int* in_sizes, int n_in,
                              void* d_out, int out_size) {
    const float* x    = (const float*)d_in[0];
    const int*   rows = (const int*)  d_in[1];
    const int*   cols = (const int*)  d_in[2];
    const float* vals = (const float*)d_in[3];
    const float* W1   = (const float*)d_in[4];
    const float* W2   = (const float*)d_in[5];
    float* out = (float*)d_out;

    const int nnz = in_sizes[1];
    const int N   = N_NODES;

    __half *xh, *ha, *hb, *h3, *w1h, *w2h;
    cudaGetSymbolAddress((void**)&xh,  g_xh);
    cudaGetSymbolAddress((void**)&ha,  g_ha);
    cudaGetSymbolAddress((void**)&hb,  g_hb);
    cudaGetSymbolAddress((void**)&h3,  g_h3);
    cudaGetSymbolAddress((void**)&w1h, g_w1h);
    cudaGetSymbolAddress((void**)&w2h, g_w2h);

    const int BT = 256;
    const int nodeBlocks = (N + BT - 1) / BT;
    const int nnzBlocks  = (nnz + BT - 1) / BT;
    const int spmmBlocks = (N * 32 + BT - 1) / BT;

    // ---- CSR build
    zero_counts_kernel<<<nodeBlocks, BT>>>();
    hist_kernel<<<nnzBlocks, BT>>>(rows, nnz);
    scan1_kernel<<<NBLK, SCAN_BS>>>();
    scan2_kernel<<<1, 32>>>();
    scan3_kernel<<<nodeBlocks, BT>>>(nnz);
    scatter_kernel<<<nnzBlocks, BT>>>(rows, cols, vals, nnz);

    // ---- fp16 conversions
    f2h_kernel<<<(N * 128 + BT - 1) / BT, BT>>>(x,  xh,  N * 128);
    f2h_kernel<<<(256 * 128 + BT - 1) / BT, BT>>>(W1, w1h, 256 * 128);
    f2h_kernel<<<(128 * 256 + BT - 1) / BT, BT>>>(W2, w2h, 128 * 256);

    // ---- layer 1 propagates (fp16)
    spmm_h_kernel<true><<<spmmBlocks, BT>>>(xh, ha, 1.0f);   // h1
    spmm_h_kernel<true><<<spmmBlocks, BT>>>(ha, hb, 1.0f);   // h2

    // ---- h3 = relu(h2 @ W1^T)  [N,256]
    {
        dim3 grid((N + 127) / 128, 256 / 64);
        gemm_tc_kernel<128, true><<<grid, 256>>>(hb, w1h, h3, N, 256, 1.0f);
    }
    // ---- g' = 1024 * (h3 @ W2^T)  [N,128]  (W2 folded before propagates)
    {
        dim3 grid((N + 127) / 128, 128 / 64);
        gemm_tc_kernel<256, false><<<grid, 256>>>(h3, w2h, ha, N, 128, GSCALE);
    }

    // ---- layer 2 propagates: t' fp16 (scaled), final fp32 with exact unscale
    spmm_h_kernel<true ><<<spmmBlocks, BT>>>(ha, hb, 1.0f);        // t' = A@g'
    spmm_h_kernel<false><<<spmmBlocks, BT>>>(hb, out, GSCALE_INV); // out = (A@t')/1024
}

// round 7
// speedup vs baseline: 2.3238x; 1.0476x over previous
#include <cuda_runtime.h>
#include <cuda_fp16.h>
#include <cuda_bf16.h>

#define N_NODES 100000
#define MAX_NNZ 3200000
#define SCAN_BS 512
#define NBLK ((N_NODES + SCAN_BS - 1) / SCAN_BS)   // 196

// Exact power-of-2 scaling for post-W2 stages (keeps t' in fp16-normal range)
#define GSCALE     1024.0f
#define GSCALE_INV (1.0f / 1024.0f)

// ---------------- scratch (no cudaMalloc allowed) ----------------
__device__ __half g_xh [(size_t)N_NODES * 128];
__device__ __half g_ha [(size_t)N_NODES * 128];
__device__ __half g_hb [(size_t)N_NODES * 128];
__device__ __half g_h3 [(size_t)N_NODES * 256];
__device__ __half g_w1h[256 * 128];
__device__ __half g_w2h[128 * 256];
__device__ int    g_count[N_NODES];
__device__ int    g_rowptr[N_NODES + 1];
__device__ int    g_wptr[N_NODES];
__device__ int    g_blocksum[NBLK];
__device__ unsigned long long g_epack[MAX_NNZ];  // (col:int32 lo, val:f32 bits hi)

// ---------------------------------------------------------------------------
// CSR build: histogram -> scan -> scatter
// ---------------------------------------------------------------------------
__global__ void hist_kernel(const int* __restrict__ rows, int nnz) {
    int i = blockIdx.x * blockDim.x + threadIdx.x;
    if (i < nnz) atomicAdd(&g_count[rows[i]], 1);
}

__global__ void scan1_kernel() {
    __shared__ int s[SCAN_BS];
    int tid = threadIdx.x;
    int i = blockIdx.x * SCAN_BS + tid;
    int v = (i < N_NODES) ? g_count[i] : 0;
    s[tid] = v;
    __syncthreads();
#pragma unroll
    for (int off = 1; off < SCAN_BS; off <<= 1) {
        int t = (tid >= off) ? s[tid - off] : 0;
        __syncthreads();
        s[tid] += t;
        __syncthreads();
    }
    if (i < N_NODES) g_rowptr[i] = s[tid] - v;           // local exclusive
    if (tid == SCAN_BS - 1) g_blocksum[blockIdx.x] = s[tid];
}

// parallel exclusive scan over NBLK block sums (one 256-thread block)
__global__ void scan2_kernel() {
    __shared__ int s[256];
    int tid = threadIdx.x;
    int v = (tid < NBLK) ? g_blocksum[tid] : 0;
    s[tid] = v;
    __syncthreads();
#pragma unroll
    for (int off = 1; off < 256; off <<= 1) {
        int t = (tid >= off) ? s[tid - off] : 0;
        __syncthreads();
        s[tid] += t;
        __syncthreads();
    }
    if (tid < NBLK) g_blocksum[tid] = s[tid] - v;        // exclusive
}

__global__ void scan3_kernel(int nnz) {
    int i = blockIdx.x * blockDim.x + threadIdx.x;
    if (i < N_NODES) {
        int rp = g_rowptr[i] + g_blocksum[i / SCAN_BS];
        g_rowptr[i] = rp;
        g_wptr[i]   = rp;
    }
    if (i == 0) g_rowptr[N_NODES] = nnz;
}

__global__ void scatter_kernel(const int* __restrict__ rows,
                               const int* __restrict__ cols,
                               const float* __restrict__ vals, int nnz) {
    int i = blockIdx.x * blockDim.x + threadIdx.x;
    if (i >= nnz) return;
    int r = rows[i];
    int pos = atomicAdd(&g_wptr[r], 1);
    unsigned vbits = __float_as_uint(vals[i]);
    g_epack[pos] = (unsigned long long)(unsigned)cols[i]
                 | ((unsigned long long)vbits << 32);
}

// ---------------------------------------------------------------------------
// fp32 -> fp16 for x, W1, W2 in one kernel
// ---------------------------------------------------------------------------
__global__ void f2h3_kernel(const float* __restrict__ x,  __half* __restrict__ xh,  int n0,
                            const float* __restrict__ w1, __half* __restrict__ w1h, int n1,
                            const float* __restrict__ w2, __half* __restrict__ w2h, int n2) {
    int i = blockIdx.x * blockDim.x + threadIdx.x;
    if (i < n0) { xh[i] = __float2half_rn(x[i]); return; }
    i -= n0;
    if (i < n1) { w1h[i] = __float2half_rn(w1[i]); return; }
    i -= n1;
    if (i < n2) { w2h[i] = __float2half_rn(w2[i]); }
}

// ---------------------------------------------------------------------------
// Gather SpMM (d=128): one warp per row, lane owns 4 features, fp32 accum.
// Packed edge: one 8B broadcast load per edge.
// ---------------------------------------------------------------------------
__device__ __forceinline__ void acc_edge(const __half* __restrict__ h, int e,
                                         int lane, float4& acc) {
    uint2 p = __ldg(reinterpret_cast<const uint2*>(&g_epack[e]));
    int   c = (int)p.x;
    float v = __uint_as_float(p.y);
    uint2 u = __ldg(reinterpret_cast<const uint2*>(h + (size_t)c * 128) + lane);
    __half2 p0 = *reinterpret_cast<__half2*>(&u.x);
    __half2 p1 = *reinterpret_cast<__half2*>(&u.y);
    float2 f0 = __half22float2(p0);
    float2 f1 = __half22float2(p1);
    acc.x = fmaf(v, f0.x, acc.x); acc.y = fmaf(v, f0.y, acc.y);
    acc.z = fmaf(v, f1.x, acc.z); acc.w = fmaf(v, f1.y, acc.w);
}

template <bool OUT_HALF>
__global__ void __launch_bounds__(256)
spmm_h_kernel(const __half* __restrict__ h, void* __restrict__ outv, float oscale) {
    int r = (blockIdx.x * blockDim.x + threadIdx.x) >> 5;
    if (r >= N_NODES) return;
    int lane = threadIdx.x & 31;

    int beg = __ldg(&g_rowptr[r]);
    int end = __ldg(&g_rowptr[r + 1]);

    float4 acc = make_float4(0.f, 0.f, 0.f, 0.f);
    int e = beg;
    for (; e + 3 < end; e += 4) {
        acc_edge(h, e,     lane, acc);
        acc_edge(h, e + 1, lane, acc);
        acc_edge(h, e + 2, lane, acc);
        acc_edge(h, e + 3, lane, acc);
    }
    for (; e < end; e++) acc_edge(h, e, lane, acc);

    acc.x *= oscale; acc.y *= oscale; acc.z *= oscale; acc.w *= oscale;

    if (OUT_HALF) {
        __half2 o0 = __floats2half2_rn(acc.x, acc.y);
        __half2 o1 = __floats2half2_rn(acc.z, acc.w);
        uint2 u;
        u.x = *reinterpret_cast<unsigned*>(&o0);
        u.y = *reinterpret_cast<unsigned*>(&o1);
        *(reinterpret_cast<uint2*>((__half*)outv + (size_t)r * 128) + lane) = u;
    } else {
        *(reinterpret_cast<float4*>((float*)outv + (size_t)r * 128) + lane) = acc;
    }
}

// ---------------------------------------------------------------------------
// Tensor-core GEMM, fully-resident tiles: stage the WHOLE 128xK A tile and
// 64xK W panel in smem, ONE sync, then K/16 barrier-free mma steps.
// C[n,j] = oscale * sum_k A[n,k]*W[j,k]; fp16 in, fp32 accum, fp16 out.
// Block 128(M) x 64(J), 8 warps (4Mx2J), warp tile 32x32 = 2x4 m16n8k16.
// Row pad = 8 halves -> fragment loads hit all 32 banks (4g+t pattern).
// ---------------------------------------------------------------------------
template <int K, bool RELU>
__global__ void gemm_tc_kernel(const __half* __restrict__ A,
                               const __half* __restrict__ W,
                               __half* __restrict__ C,
                               int N, int J, float oscale) {
    constexpr int LDS = K + 8;
    extern __shared__ __half smem[];
    __half (*As)[LDS] = reinterpret_cast<__half(*)[LDS]>(smem);
    __half (*Ws)[LDS] = reinterpret_cast<__half(*)[LDS]>(smem + 128 * LDS);

    const int tid  = threadIdx.x;      // 0..255
    const int lane = tid & 31;
    const int wid  = tid >> 5;
    const int warpM = wid & 3;
    const int warpJ = wid >> 2;
    const int gid = lane >> 2;         // 0..7
    const int tig = lane & 3;          // 0..3

    const int rowBase = blockIdx.x * 128;
    const int colBase = blockIdx.y * 64;

    // ---- stage entire A tile (128 x K) and W panel (64 x K)
    constexpr int SEGS = K / 8;        // uint4 chunks per row
    for (int i = tid; i < 128 * SEGS; i += 256) {
        int row = i / SEGS, seg = (i % SEGS) * 8;
        uint4 v = make_uint4(0, 0, 0, 0);
        int arow = rowBase + row;
        if (arow < N)
            v = *reinterpret_cast<const uint4*>(A + (size_t)arow * K + seg);
        *reinterpret_cast<uint4*>(&As[row][seg]) = v;
    }
    for (int i = tid; i < 64 * SEGS; i += 256) {
        int row = i / SEGS, seg = (i % SEGS) * 8;
        *reinterpret_cast<uint4*>(&Ws[row][seg]) =
            *reinterpret_cast<const uint4*>(W + (size_t)(colBase + row) * K + seg);
    }
    __syncthreads();

    float acc[2][4][4];
#pragma unroll
    for (int m = 0; m < 2; m++)
#pragma unroll
        for (int n = 0; n < 4; n++)
#pragma unroll
            for (int q = 0; q < 4; q++) acc[m][n][q] = 0.f;

    // ---- barrier-free mainloop
#pragma unroll
    for (int k0 = 0; k0 < K; k0 += 16) {
        unsigned a[2][4], b[4][2];
#pragma unroll
        for (int m = 0; m < 2; m++) {
            int r0 = warpM * 32 + m * 16 + gid;
            a[m][0] = *reinterpret_cast<const unsigned*>(&As[r0    ][k0 + tig * 2    ]);
            a[m][1] = *reinterpret_cast<const unsigned*>(&As[r0 + 8][k0 + tig * 2    ]);
            a[m][2] = *reinterpret_cast<const unsigned*>(&As[r0    ][k0 + tig * 2 + 8]);
            a[m][3] = *reinterpret_cast<const unsigned*>(&As[r0 + 8][k0 + tig * 2 + 8]);
        }
#pragma unroll
        for (int n = 0; n < 4; n++) {
            int jr = warpJ * 32 + n * 8 + gid;
            b[n][0] = *reinterpret_cast<const unsigned*>(&Ws[jr][k0 + tig * 2    ]);
            b[n][1] = *reinterpret_cast<const unsigned*>(&Ws[jr][k0 + tig * 2 + 8]);
        }
#pragma unroll
        for (int m = 0; m < 2; m++)
#pragma unroll
            for (int n = 0; n < 4; n++) {
                asm volatile(
                    "mma.sync.aligned.m16n8k16.row.col.f32.f16.f16.f32 "
                    "{%0,%1,%2,%3}, {%4,%5,%6,%7}, {%8,%9}, {%0,%1,%2,%3};\n"
                    : "+f"(acc[m][n][0]), "+f"(acc[m][n][1]),
                      "+f"(acc[m][n][2]), "+f"(acc[m][n][3])
                    : "r"(a[m][0]), "r"(a[m][1]), "r"(a[m][2]), "r"(a[m][3]),
                      "r"(b[n][0]), "r"(b[n][1]));
            }
    }

    // ---- epilogue: c0,c1 -> row gid; c2,c3 -> row gid+8; cols tig*2, tig*2+1
#pragma unroll
    for (int m = 0; m < 2; m++) {
        int rbase = rowBase + warpM * 32 + m * 16;
#pragma unroll
        for (int n = 0; n < 4; n++) {
            int col = colBase + warpJ * 32 + n * 8 + tig * 2;
            float v0 = acc[m][n][0], v1 = acc[m][n][1];
            float v2 = acc[m][n][2], v3 = acc[m][n][3];
            if (RELU) {
                v0 = fmaxf(v0, 0.f); v1 = fmaxf(v1, 0.f);
                v2 = fmaxf(v2, 0.f); v3 = fmaxf(v3, 0.f);
            }
            v0 *= oscale; v1 *= oscale; v2 *= oscale; v3 *= oscale;
            int r0 = rbase + gid;
            int r1 = rbase + gid + 8;
            if (r0 < N) {
                __half2 p = __floats2half2_rn(v0, v1);
                *reinterpret_cast<__half2*>(C + (size_t)r0 * J + col) = p;
            }
            if (r1 < N) {
                __half2 p = __floats2half2_rn(v2, v3);
                *reinterpret_cast<__half2*>(C + (size_t)r1 * J + col) = p;
            }
        }
    }
}

// ---------------------------------------------------------------------------
// Sequence:
//   CSR build; fp16 converts
//   h1 = A@xh; h2 = A@h1
//   h3 = relu(h2 @ W1^T) [N,256];  g' = 1024*(h3 @ W2^T) [N,128]
//   t' = A@g';  out = (A@t')/1024  (fp32)
// ---------------------------------------------------------------------------
extern "C" void kernel_launch(void* const* d_in, const int* in_sizes, int n_in,
                              void* d_out, int out_size) {
    const float* x    = (const float*)d_in[0];
    const int*   rows = (const int*)  d_in[1];
    const int*   cols = (const int*)  d_in[2];
    const float* vals = (const float*)d_in[3];
    const float* W1   = (const float*)d_in[4];
    const float* W2   = (const float*)d_in[5];
    float* out = (float*)d_out;

    const int nnz = in_sizes[1];
    const int N   = N_NODES;

    __half *xh, *ha, *hb, *h3, *w1h, *w2h;
    int *cnt;
    cudaGetSymbolAddress((void**)&xh,  g_xh);
    cudaGetSymbolAddress((void**)&ha,  g_ha);
    cudaGetSymbolAddress((void**)&hb,  g_hb);
    cudaGetSymbolAddress((void**)&h3,  g_h3);
    cudaGetSymbolAddress((void**)&w1h, g_w1h);
    cudaGetSymbolAddress((void**)&w2h, g_w2h);
    cudaGetSymbolAddress((void**)&cnt, g_count);

    const int BT = 256;
    const int nodeBlocks = (N + BT - 1) / BT;
    const int nnzBlocks  = (nnz + BT - 1) / BT;
    const int spmmBlocks = (N * 32 + BT - 1) / BT;

    // smem sizes for the resident-tile GEMMs (set attrs unconditionally —
    // idempotent, no static guards allowed)
    const int smem128 = (128 + 64) * (128 + 8) * (int)sizeof(__half);  // 52,224 B
    const int smem256 = (128 + 64) * (256 + 8) * (int)sizeof(__half);  // 101,376 B
    cudaFuncSetAttribute(gemm_tc_kernel<128, true>,
                         cudaFuncAttributeMaxDynamicSharedMemorySize, smem128);
    cudaFuncSetAttribute(gemm_tc_kernel<256, false>,
                         cudaFuncAttributeMaxDynamicSharedMemorySize, smem256);

    // ---- CSR build
    cudaMemsetAsync(cnt, 0, N * sizeof(int));
    hist_kernel<<<nnzBlocks, BT>>>(rows, nnz);
    scan1_kernel<<<NBLK, SCAN_BS>>>();
    scan2_kernel<<<1, 256>>>();
    scan3_kernel<<<nodeBlocks, BT>>>(nnz);
    scatter_kernel<<<nnzBlocks, BT>>>(rows, cols, vals, nnz);

    // ---- fp16 conversions (single kernel)
    {
        int n0 = N * 128, n1 = 256 * 128, n2 = 128 * 256;
        int tot = n0 + n1 + n2;
        f2h3_kernel<<<(tot + BT - 1) / BT, BT>>>(x, xh, n0, W1, w1h, n1, W2, w2h, n2);
    }

    // ---- layer 1 propagates
    spmm_h_kernel<true><<<spmmBlocks, BT>>>(xh, ha, 1.0f);   // h1
    spmm_h_kernel<true><<<spmmBlocks, BT>>>(ha, hb, 1.0f);   // h2

    // ---- h3 = relu(h2 @ W1^T)  [N,256]
    {
        dim3 grid((N + 127) / 128, 256 / 64);
        gemm_tc_kernel<128, true><<<grid, 256, smem128>>>(hb, w1h, h3, N, 256, 1.0f);
    }
    // ---- g' = 1024 * (h3 @ W2^T)  [N,128]
    {
        dim3 grid((N + 127) / 128, 128 / 64);
        gemm_tc_kernel<256, false><<<grid, 256, smem256>>>(h3, w2h, ha, N, 128, GSCALE);
    }

    // ---- layer 2 propagates
    spmm_h_kernel<true ><<<spmmBlocks, BT>>>(ha, hb, 1.0f);        // t' = A@g'
    spmm_h_kernel<false><<<spmmBlocks, BT>>>(hb, out, GSCALE_INV); // out = (A@t')/1024
}

// round 9
// speedup vs baseline: 2.6108x; 1.1235x over previous
#include <cuda_runtime.h>
#include <cuda_fp16.h>
#include <cuda_bf16.h>

#define N_NODES 100000
#define MAX_NNZ 3200000
#define ELL_CAP 128   // slots/row; Poisson(32) => P(deg>=128) ~ e^-88, never hit

// Exact power-of-2 scaling for post-W2 stages (keeps t' in fp16-normal range)
#define GSCALE     1024.0f
#define GSCALE_INV (1.0f / 1024.0f)

// ---------------- scratch (no cudaMalloc allowed) ----------------
__device__ __half g_xh [(size_t)N_NODES * 128];
__device__ __half g_ha [(size_t)N_NODES * 128];
__device__ __half g_hb [(size_t)N_NODES * 128];
__device__ __half g_w1h[256 * 128];
__device__ __half g_w2h[128 * 256];
__device__ int    g_cnt[N_NODES];
__device__ unsigned long long g_ell[(size_t)N_NODES * ELL_CAP]; // (col lo, val bits hi)

// ---------------------------------------------------------------------------
// Prep: ELL scatter + fp32->fp16 converts for x, W1, W2 — one kernel.
// ---------------------------------------------------------------------------
__global__ void prep_kernel(const int* __restrict__ rows,
                            const int* __restrict__ cols,
                            const float* __restrict__ vals, int nnz,
                            const float* __restrict__ x,  int n0,
                            const float* __restrict__ w1, int n1,
                            const float* __restrict__ w2, int n2) {
    int i = blockIdx.x * blockDim.x + threadIdx.x;
    if (i < nnz) {
        int r = rows[i];
        int pos = atomicAdd(&g_cnt[r], 1);
        if (pos < ELL_CAP) {
            unsigned vbits = __float_as_uint(vals[i]);
            g_ell[(size_t)r * ELL_CAP + pos] =
                (unsigned long long)(unsigned)cols[i]
              | ((unsigned long long)vbits << 32);
        }
        return;
    }
    i -= nnz;
    if (i < n0) { g_xh[i]  = __float2half_rn(x[i]);  return; }
    i -= n0;
    if (i < n1) { g_w1h[i] = __float2half_rn(w1[i]); return; }
    i -= n1;
    if (i < n2) { g_w2h[i] = __float2half_rn(w2[i]); }
}

// ---------------------------------------------------------------------------
// Gather SpMM (d=128): one warp per row, lane owns 4 features, fp32 accum.
// ELL edges: contiguous 8B entries at r*ELL_CAP, count from g_cnt[r].
// ---------------------------------------------------------------------------
__device__ __forceinline__ void acc_edge(const __half* __restrict__ h,
                                         const unsigned long long* __restrict__ ebase,
                                         int e, int lane, float4& acc) {
    uint2 p = __ldg(reinterpret_cast<const uint2*>(ebase + e));
    int   c = (int)p.x;
    float v = __uint_as_float(p.y);
    uint2 u = __ldg(reinterpret_cast<const uint2*>(h + (size_t)c * 128) + lane);
    __half2 p0 = *reinterpret_cast<__half2*>(&u.x);
    __half2 p1 = *reinterpret_cast<__half2*>(&u.y);
    float2 f0 = __half22float2(p0);
    float2 f1 = __half22float2(p1);
    acc.x = fmaf(v, f0.x, acc.x); acc.y = fmaf(v, f0.y, acc.y);
    acc.z = fmaf(v, f1.x, acc.z); acc.w = fmaf(v, f1.y, acc.w);
}

template <bool OUT_HALF>
__global__ void __launch_bounds__(256)
spmm_ell_kernel(const __half* __restrict__ h, void* __restrict__ outv, float oscale) {
    int r = (blockIdx.x * blockDim.x + threadIdx.x) >> 5;
    if (r >= N_NODES) return;
    int lane = threadIdx.x & 31;

    int cnt = __ldg(&g_cnt[r]);
    if (cnt > ELL_CAP) cnt = ELL_CAP;
    const unsigned long long* ebase = g_ell + (size_t)r * ELL_CAP;

    float4 acc = make_float4(0.f, 0.f, 0.f, 0.f);
    int e = 0;
    for (; e + 3 < cnt; e += 4) {
        acc_edge(h, ebase, e,     lane, acc);
        acc_edge(h, ebase, e + 1, lane, acc);
        acc_edge(h, ebase, e + 2, lane, acc);
        acc_edge(h, ebase, e + 3, lane, acc);
    }
    for (; e < cnt; e++) acc_edge(h, ebase, e, lane, acc);

    acc.x *= oscale; acc.y *= oscale; acc.z *= oscale; acc.w *= oscale;

    if (OUT_HALF) {
        __half2 o0 = __floats2half2_rn(acc.x, acc.y);
        __half2 o1 = __floats2half2_rn(acc.z, acc.w);
        uint2 u;
        u.x = *reinterpret_cast<unsigned*>(&o0);
        u.y = *reinterpret_cast<unsigned*>(&o1);
        *(reinterpret_cast<uint2*>((__half*)outv + (size_t)r * 128) + lane) = u;
    } else {
        *(reinterpret_cast<float4*>((float*)outv + (size_t)r * 128) + lane) = acc;
    }
}

// ---------------------------------------------------------------------------
// Fused MLP: C[n,:] = GSCALE * ( relu(A[n,:] @ W1^T) @ W2^T ),  [N,128]
// A: h2 [N,128] fp16; W1 [256,128]; W2 [128,256]; C fp16.
// Per 128-row block: stage A once; loop 4 chunks of 64 h3-features:
//   load W1 chunk (64x128) + W2 chunk (128x64) -> GEMM1 -> relu -> P fp16 smem
//   -> GEMM2 accumulate into out regs. One kernel, no h3 round-trip.
// 8 warps as 4(M)x2(J). GEMM1 warp tile 32x32; GEMM2 warp tile 32x64.
// LDSA=136, LDSP=72: both == 4 banks mod 32 -> fragment loads conflict-free.
// ---------------------------------------------------------------------------
#define LDSA 136
#define LDSP 72

__global__ void __launch_bounds__(256)
fused_mlp_kernel(const __half* __restrict__ A,
                 const __half* __restrict__ W1,
                 const __half* __restrict__ W2,
                 __half* __restrict__ C, int N) {
    extern __shared__ __half sm[];
    __half (*As) [LDSA] = reinterpret_cast<__half(*)[LDSA]>(sm);                  // 128x136
    __half (*W1s)[LDSA] = reinterpret_cast<__half(*)[LDSA]>(sm + 128 * LDSA);     // 64x136
    __half (*Ps) [LDSP] = reinterpret_cast<__half(*)[LDSP]>(sm + 192 * LDSA);     // 128x72
    __half (*W2s)[LDSP] = reinterpret_cast<__half(*)[LDSP]>(sm + 192 * LDSA + 128 * LDSP); // 128x72

    const int tid  = threadIdx.x;
    const int lane = tid & 31;
    const int wid  = tid >> 5;
    const int warpM = wid & 3;
    const int warpJ = wid >> 2;
    const int gid = lane >> 2;
    const int tig = lane & 3;

    const int rowBase = blockIdx.x * 128;

    // ---- stage A tile (128 x 128)
    for (int i = tid; i < 128 * 16; i += 256) {
        int row = i >> 4, seg = (i & 15) * 8;
        uint4 v = make_uint4(0, 0, 0, 0);
        int arow = rowBase + row;
        if (arow < N)
            v = *reinterpret_cast<const uint4*>(A + (size_t)arow * 128 + seg);
        *reinterpret_cast<uint4*>(&As[row][seg]) = v;
    }

    float oacc[2][8][4];
#pragma unroll
    for (int m = 0; m < 2; m++)
#pragma unroll
        for (int n = 0; n < 8; n++)
#pragma unroll
            for (int q = 0; q < 4; q++) oacc[m][n][q] = 0.f;

    for (int kc = 0; kc < 4; kc++) {
        // ---- load W1 chunk: rows kc*64..+64 (of 256), all 128 cols
        for (int i = tid; i < 64 * 16; i += 256) {
            int row = i >> 4, seg = (i & 15) * 8;
            *reinterpret_cast<uint4*>(&W1s[row][seg]) =
                *reinterpret_cast<const uint4*>(W1 + (size_t)(kc * 64 + row) * 128 + seg);
        }
        // ---- load W2 chunk: all 128 rows, cols kc*64..+64 (of 256)
        for (int i = tid; i < 128 * 8; i += 256) {
            int row = i >> 3, seg = (i & 7) * 8;
            *reinterpret_cast<uint4*>(&W2s[row][seg]) =
                *reinterpret_cast<const uint4*>(W2 + (size_t)row * 256 + kc * 64 + seg);
        }
        __syncthreads();

        // ---- GEMM1: pacc = As @ W1s^T   (warp tile 32x32, K=128)
        float pacc[2][4][4];
#pragma unroll
        for (int m = 0; m < 2; m++)
#pragma unroll
            for (int n = 0; n < 4; n++)
#pragma unroll
                for (int q = 0; q < 4; q++) pacc[m][n][q] = 0.f;

#pragma unroll
        for (int k0 = 0; k0 < 128; k0 += 16) {
            unsigned a[2][4], b[4][2];
#pragma unroll
            for (int m = 0; m < 2; m++) {
                int r0 = warpM * 32 + m * 16 + gid;
                a[m][0] = *reinterpret_cast<const unsigned*>(&As[r0    ][k0 + tig * 2    ]);
                a[m][1] = *reinterpret_cast<const unsigned*>(&As[r0 + 8][k0 + tig * 2    ]);
                a[m][2] = *reinterpret_cast<const unsigned*>(&As[r0    ][k0 + tig * 2 + 8]);
                a[m][3] = *reinterpret_cast<const unsigned*>(&As[r0 + 8][k0 + tig * 2 + 8]);
            }
#pragma unroll
            for (int n = 0; n < 4; n++) {
                int jr = warpJ * 32 + n * 8 + gid;
                b[n][0] = *reinterpret_cast<const unsigned*>(&W1s[jr][k0 + tig * 2    ]);
                b[n][1] = *reinterpret_cast<const unsigned*>(&W1s[jr][k0 + tig * 2 + 8]);
            }
#pragma unroll
            for (int m = 0; m < 2; m++)
#pragma unroll
                for (int n = 0; n < 4; n++) {
                    asm volatile(
                        "mma.sync.aligned.m16n8k16.row.col.f32.f16.f16.f32 "
                        "{%0,%1,%2,%3}, {%4,%5,%6,%7}, {%8,%9}, {%0,%1,%2,%3};\n"
                        : "+f"(pacc[m][n][0]), "+f"(pacc[m][n][1]),
                          "+f"(pacc[m][n][2]), "+f"(pacc[m][n][3])
                        : "r"(a[m][0]), "r"(a[m][1]), "r"(a[m][2]), "r"(a[m][3]),
                          "r"(b[n][0]), "r"(b[n][1]));
                }
        }

        // ---- relu + fp16 -> Ps  (c0,c1 -> row gid; c2,c3 -> row gid+8)
#pragma unroll
        for (int m = 0; m < 2; m++) {
            int rbase = warpM * 32 + m * 16;
#pragma unroll
            for (int n = 0; n < 4; n++) {
                int col = warpJ * 32 + n * 8 + tig * 2;
                float v0 = fmaxf(pacc[m][n][0], 0.f), v1 = fmaxf(pacc[m][n][1], 0.f);
                float v2 = fmaxf(pacc[m][n][2], 0.f), v3 = fmaxf(pacc[m][n][3], 0.f);
                *reinterpret_cast<__half2*>(&Ps[rbase + gid    ][col]) = __floats2half2_rn(v0, v1);
                *reinterpret_cast<__half2*>(&Ps[rbase + gid + 8][col]) = __floats2half2_rn(v2, v3);
            }
        }
        __syncthreads();

        // ---- GEMM2: oacc += Ps @ W2s^T  (warp tile 32x64, K=64)
#pragma unroll
        for (int k0 = 0; k0 < 64; k0 += 16) {
            unsigned a[2][4], b[8][2];
#pragma unroll
            for (int m = 0; m < 2; m++) {
                int r0 = warpM * 32 + m * 16 + gid;
                a[m][0] = *reinterpret_cast<const unsigned*>(&Ps[r0    ][k0 + tig * 2    ]);
                a[m][1] = *reinterpret_cast<const unsigned*>(&Ps[r0 + 8][k0 + tig * 2    ]);
                a[m][2] = *reinterpret_cast<const unsigned*>(&Ps[r0    ][k0 + tig * 2 + 8]);
                a[m][3] = *reinterpret_cast<const unsigned*>(&Ps[r0 + 8][k0 + tig * 2 + 8]);
            }
#pragma unroll
            for (int n = 0; n < 8; n++) {
                int jr = warpJ * 64 + n * 8 + gid;
                b[n][0] = *reinterpret_cast<const unsigned*>(&W2s[jr][k0 + tig * 2    ]);
                b[n][1] = *reinterpret_cast<const unsigned*>(&W2s[jr][k0 + tig * 2 + 8]);
            }
#pragma unroll
            for (int m = 0; m < 2; m++)
#pragma unroll
                for (int n = 0; n < 8; n++) {
                    asm volatile(
                        "mma.sync.aligned.m16n8k16.row.col.f32.f16.f16.f32 "
                        "{%0,%1,%2,%3}, {%4,%5,%6,%7}, {%8,%9}, {%0,%1,%2,%3};\n"
                        : "+f"(oacc[m][n][0]), "+f"(oacc[m][n][1]),
                          "+f"(oacc[m][n][2]), "+f"(oacc[m][n][3])
                        : "r"(a[m][0]), "r"(a[m][1]), "r"(a[m][2]), "r"(a[m][3]),
                          "r"(b[n][0]), "r"(b[n][1]));
                }
        }
        __syncthreads();   // before next chunk overwrites W1s/W2s/Ps
    }

    // ---- epilogue: C = GSCALE * oacc  (fp16), cols warpJ*64 + n*8 + tig*2
#pragma unroll
    for (int m = 0; m < 2; m++) {
        int rbase = rowBase + warpM * 32 + m * 16;
#pragma unroll
        for (int n = 0; n < 8; n++) {
            int col = warpJ * 64 + n * 8 + tig * 2;
            float v0 = oacc[m][n][0] * GSCALE, v1 = oacc[m][n][1] * GSCALE;
            float v2 = oacc[m][n][2] * GSCALE, v3 = oacc[m][n][3] * GSCALE;
            int r0 = rbase + gid;
            int r1 = rbase + gid + 8;
            if (r0 < N)
                *reinterpret_cast<__half2*>(C + (size_t)r0 * 128 + col) = __floats2half2_rn(v0, v1);
            if (r1 < N)
                *reinterpret_cast<__half2*>(C + (size_t)r1 * 128 + col) = __floats2half2_rn(v2, v3);
        }
    }
}

// ---------------------------------------------------------------------------
// Sequence:
//   memset cnt; prep (ELL scatter + fp16 converts)
//   h1 = A@xh; h2 = A@h1
//   g' = 1024*relu(h2@W1^T)@W2^T   (fused, one kernel)
//   t' = A@g';  out = (A@t')/1024  (fp32)
// ---------------------------------------------------------------------------
extern "C" void kernel_launch(void* const* d_in, const int* in_sizes, int n_in,
                              void* d_out, int out_size) {
    const float* x    = (const float*)d_in[0];
    const int*   rows = (const int*)  d_in[1];
    const int*   cols = (const int*)  d_in[2];
    const float* vals = (const float*)d_in[3];
    const float* W1   = (const float*)d_in[4];
    const float* W2   = (const float*)d_in[5];
    float* out = (float*)d_out;

    const int nnz = in_sizes[1];
    const int N   = N_NODES;

    __half *xh, *ha, *hb, *w1h, *w2h;
    int *cnt;
    cudaGetSymbolAddress((void**)&xh,  g_xh);
    cudaGetSymbolAddress((void**)&ha,  g_ha);
    cudaGetSymbolAddress((void**)&hb,  g_hb);
    cudaGetSymbolAddress((void**)&w1h, g_w1h);
    cudaGetSymbolAddress((void**)&w2h, g_w2h);
    cudaGetSymbolAddress((void**)&cnt, g_cnt);

    const int BT = 256;
    const int spmmBlocks = (N * 32 + BT - 1) / BT;

    // fused kernel smem: (128+64)*136 + (128+128)*72 halves = 44,544 h = 89,088 B
    const int smemFused = (192 * LDSA + 256 * LDSP) * (int)sizeof(__half);
    cudaFuncSetAttribute(fused_mlp_kernel,
                         cudaFuncAttributeMaxDynamicSharedMemorySize, smemFused);

    // ---- ELL build + converts
    cudaMemsetAsync(cnt, 0, N * sizeof(int));
    {
        int n0 = N * 128, n1 = 256 * 128, n2 = 128 * 256;
        long long tot = (long long)nnz + n0 + n1 + n2;
        prep_kernel<<<(int)((tot + BT - 1) / BT), BT>>>(rows, cols, vals, nnz,
                                                        x, n0, W1, n1, W2, n2);
    }

    // ---- layer 1 propagates
    spmm_ell_kernel<true><<<spmmBlocks, BT>>>(xh, ha, 1.0f);   // h1
    spmm_ell_kernel<true><<<spmmBlocks, BT>>>(ha, hb, 1.0f);   // h2

    // ---- fused MLP: g' = 1024 * relu(h2@W1^T)@W2^T  -> ha
    fused_mlp_kernel<<<(N + 127) / 128, 256, smemFused>>>(hb, w1h, w2h, ha, N);

    // ---- layer 2 propagates
    spmm_ell_kernel<true ><<<spmmBlocks, BT>>>(ha, hb, 1.0f);        // t' = A@g'
    spmm_ell_kernel<false><<<spmmBlocks, BT>>>(hb, out, GSCALE_INV); // out = (A@t')/1024
}

// round 11
// speedup vs baseline: 2.6979x; 1.0334x over previous
#include <cuda_runtime.h>
#include <cuda_fp16.h>
#include <cuda_bf16.h>

#define N_NODES 100000
#define MAX_NNZ 3200000
#define ELL_CAP 128   // slots/row; Poisson(32) => P(deg>=128) ~ e^-88, never hit

// Exact power-of-2 scaling for post-W2 stages (keeps t' in fp16-normal range)
#define GSCALE     1024.0f
#define GSCALE_INV (1.0f / 1024.0f)

// ---------------- scratch (no cudaMalloc allowed) ----------------
__device__ __half g_xh [(size_t)N_NODES * 128];
__device__ __half g_ha [(size_t)N_NODES * 128];
__device__ __half g_hb [(size_t)N_NODES * 128];
__device__ __half g_w1h[256 * 128];
__device__ __half g_w2h[128 * 256];
__device__ int    g_cnt[N_NODES];
__device__ unsigned long long g_ell[(size_t)N_NODES * ELL_CAP]; // (col lo, val bits hi)

// ---------------------------------------------------------------------------
// Prep: ELL scatter + fp32->fp16 converts (vectorized, float2 -> half2).
// All converted sizes are even, so the pair path is exact.
// ---------------------------------------------------------------------------
__global__ void prep_kernel(const int* __restrict__ rows,
                            const int* __restrict__ cols,
                            const float* __restrict__ vals, int nnz,
                            const float* __restrict__ x,  int p0,   // pairs
                            const float* __restrict__ w1, int p1,
                            const float* __restrict__ w2, int p2) {
    int i = blockIdx.x * blockDim.x + threadIdx.x;
    if (i < nnz) {
        int r = rows[i];
        int pos = atomicAdd(&g_cnt[r], 1);
        if (pos < ELL_CAP) {
            unsigned vbits = __float_as_uint(vals[i]);
            g_ell[(size_t)r * ELL_CAP + pos] =
                (unsigned long long)(unsigned)cols[i]
              | ((unsigned long long)vbits << 32);
        }
        return;
    }
    i -= nnz;
    if (i < p0) {
        float2 f = reinterpret_cast<const float2*>(x)[i];
        reinterpret_cast<__half2*>(g_xh)[i] = __floats2half2_rn(f.x, f.y);
        return;
    }
    i -= p0;
    if (i < p1) {
        float2 f = reinterpret_cast<const float2*>(w1)[i];
        reinterpret_cast<__half2*>(g_w1h)[i] = __floats2half2_rn(f.x, f.y);
        return;
    }
    i -= p1;
    if (i < p2) {
        float2 f = reinterpret_cast<const float2*>(w2)[i];
        reinterpret_cast<__half2*>(g_w2h)[i] = __floats2half2_rn(f.x, f.y);
    }
}

// ---------------------------------------------------------------------------
// Gather SpMM (d=128): one warp per row, lane owns 4 features, fp32 accum.
// ---------------------------------------------------------------------------
__device__ __forceinline__ void acc_edge(const __half* __restrict__ h,
                                         const unsigned long long* __restrict__ ebase,
                                         int e, int lane, float4& acc) {
    uint2 p = __ldg(reinterpret_cast<const uint2*>(ebase + e));
    int   c = (int)p.x;
    float v = __uint_as_float(p.y);
    uint2 u = __ldg(reinterpret_cast<const uint2*>(h + (size_t)c * 128) + lane);
    __half2 p0 = *reinterpret_cast<__half2*>(&u.x);
    __half2 p1 = *reinterpret_cast<__half2*>(&u.y);
    float2 f0 = __half22float2(p0);
    float2 f1 = __half22float2(p1);
    acc.x = fmaf(v, f0.x, acc.x); acc.y = fmaf(v, f0.y, acc.y);
    acc.z = fmaf(v, f1.x, acc.z); acc.w = fmaf(v, f1.y, acc.w);
}

template <bool OUT_HALF>
__global__ void __launch_bounds__(256)
spmm_ell_kernel(const __half* __restrict__ h, void* __restrict__ outv, float oscale) {
    int r = (blockIdx.x * blockDim.x + threadIdx.x) >> 5;
    if (r >= N_NODES) return;
    int lane = threadIdx.x & 31;

    int cnt = __ldg(&g_cnt[r]);
    if (cnt > ELL_CAP) cnt = ELL_CAP;
    const unsigned long long* ebase = g_ell + (size_t)r * ELL_CAP;

    float4 acc = make_float4(0.f, 0.f, 0.f, 0.f);
    int e = 0;
    for (; e + 3 < cnt; e += 4) {
        acc_edge(h, ebase, e,     lane, acc);
        acc_edge(h, ebase, e + 1, lane, acc);
        acc_edge(h, ebase, e + 2, lane, acc);
        acc_edge(h, ebase, e + 3, lane, acc);
    }
    for (; e < cnt; e++) acc_edge(h, ebase, e, lane, acc);

    acc.x *= oscale; acc.y *= oscale; acc.z *= oscale; acc.w *= oscale;

    if (OUT_HALF) {
        __half2 o0 = __floats2half2_rn(acc.x, acc.y);
        __half2 o1 = __floats2half2_rn(acc.z, acc.w);
        uint2 u;
        u.x = *reinterpret_cast<unsigned*>(&o0);
        u.y = *reinterpret_cast<unsigned*>(&o1);
        *(reinterpret_cast<uint2*>((__half*)outv + (size_t)r * 128) + lane) = u;
    } else {
        *(reinterpret_cast<float4*>((float*)outv + (size_t)r * 128) + lane) = acc;
    }
}

// ---------------------------------------------------------------------------
// ldmatrix helper (non-trans; A and B operands share the same lane->(row,k)
// distribution because W is [J,K] row-major with k contiguous)
// ---------------------------------------------------------------------------
__device__ __forceinline__ void ldsm_x4(unsigned* d, unsigned addr) {
    asm volatile("ldmatrix.sync.aligned.m8n8.x4.shared.b16 {%0,%1,%2,%3}, [%4];"
                 : "=r"(d[0]), "=r"(d[1]), "=r"(d[2]), "=r"(d[3]) : "r"(addr));
}

// ---------------------------------------------------------------------------
// Fused MLP: C = GSCALE * ( relu(A @ W1^T) @ W2^T ),  [N,128], fp16.
// Per 128-row block: stage A once; 4 chunks of 64 h3-features:
//   W1/W2 chunk -> GEMM1 -> relu -> Ps(fp16 smem) -> GEMM2 accumulate.
// All fragments via ldmatrix.x4. LDSA=136 / LDSP=72 halves: row stride ==
// 4 banks mod 32 -> ldmatrix phases conflict-free. 2 CTAs/SM.
// ---------------------------------------------------------------------------
#define LDSA 136
#define LDSP 72

__global__ void __launch_bounds__(256, 2)
fused_mlp_kernel(const __half* __restrict__ A,
                 const __half* __restrict__ W1,
                 const __half* __restrict__ W2,
                 __half* __restrict__ C, int N) {
    extern __shared__ __half sm[];
    __half (*As) [LDSA] = reinterpret_cast<__half(*)[LDSA]>(sm);                  // 128x136
    __half (*W1s)[LDSA] = reinterpret_cast<__half(*)[LDSA]>(sm + 128 * LDSA);     // 64x136
    __half (*Ps) [LDSP] = reinterpret_cast<__half(*)[LDSP]>(sm + 192 * LDSA);     // 128x72
    __half (*W2s)[LDSP] = reinterpret_cast<__half(*)[LDSP]>(sm + 192 * LDSA + 128 * LDSP); // 128x72

    const int tid  = threadIdx.x;
    const int lane = tid & 31;
    const int wid  = tid >> 5;
    const int warpM = wid & 3;
    const int warpJ = wid >> 2;
    const int gid = lane >> 2;
    const int tig = lane & 3;

    const int rowBase = blockIdx.x * 128;

    // ldmatrix lane-address components:
    const int lane15 = lane & 15;                 // A-style: row within 16
    const int laneK8 = (lane & 16) ? 8 : 0;       // A-style: k-offset for mats 2/3
    const int laneJ  = ((lane & 16) ? 8 : 0) + (lane & 7);  // B-style row
    const int laneBK = (lane & 8) ? 8 : 0;        // B-style k-offset

    // ---- stage A tile (128 x 128)
    for (int i = tid; i < 128 * 16; i += 256) {
        int row = i >> 4, seg = (i & 15) * 8;
        uint4 v = make_uint4(0, 0, 0, 0);
        int arow = rowBase + row;
        if (arow < N)
            v = *reinterpret_cast<const uint4*>(A + (size_t)arow * 128 + seg);
        *reinterpret_cast<uint4*>(&As[row][seg]) = v;
    }

    const unsigned aBase  = (unsigned)__cvta_generic_to_shared(&As [warpM * 32 + lane15][laneK8]);
    const unsigned w1Base = (unsigned)__cvta_generic_to_shared(&W1s[warpJ * 32 + laneJ ][laneBK]);
    const unsigned pBase  = (unsigned)__cvta_generic_to_shared(&Ps [warpM * 32 + lane15][laneK8]);
    const unsigned w2Base = (unsigned)__cvta_generic_to_shared(&W2s[warpJ * 64 + laneJ ][laneBK]);

    float oacc[2][8][4];
#pragma unroll
    for (int m = 0; m < 2; m++)
#pragma unroll
        for (int n = 0; n < 8; n++)
#pragma unroll
            for (int q = 0; q < 4; q++) oacc[m][n][q] = 0.f;

    for (int kc = 0; kc < 4; kc++) {
        // ---- load W1 chunk: rows kc*64..+64 (of 256), all 128 cols
        for (int i = tid; i < 64 * 16; i += 256) {
            int row = i >> 4, seg = (i & 15) * 8;
            *reinterpret_cast<uint4*>(&W1s[row][seg]) =
                *reinterpret_cast<const uint4*>(W1 + (size_t)(kc * 64 + row) * 128 + seg);
        }
        // ---- load W2 chunk: all 128 rows, cols kc*64..+64 (of 256)
        for (int i = tid; i < 128 * 8; i += 256) {
            int row = i >> 3, seg = (i & 7) * 8;
            *reinterpret_cast<uint4*>(&W2s[row][seg]) =
                *reinterpret_cast<const uint4*>(W2 + (size_t)row * 256 + kc * 64 + seg);
        }
        __syncthreads();

        // ---- GEMM1: pacc = As @ W1s^T   (warp tile 32x32, K=128)
        float pacc[2][4][4];
#pragma unroll
        for (int m = 0; m < 2; m++)
#pragma unroll
            for (int n = 0; n < 4; n++)
#pragma unroll
                for (int q = 0; q < 4; q++) pacc[m][n][q] = 0.f;

#pragma unroll
        for (int k0 = 0; k0 < 128; k0 += 16) {
            unsigned a[2][4], b[4][2];
#pragma unroll
            for (int m = 0; m < 2; m++)
                ldsm_x4(a[m], aBase + (unsigned)((m * 16 * LDSA + k0) * 2));
#pragma unroll
            for (int p = 0; p < 2; p++) {
                unsigned d[4];
                ldsm_x4(d, w1Base + (unsigned)((p * 16 * LDSA + k0) * 2));
                b[2 * p][0] = d[0]; b[2 * p][1] = d[1];
                b[2 * p + 1][0] = d[2]; b[2 * p + 1][1] = d[3];
            }
#pragma unroll
            for (int m = 0; m < 2; m++)
#pragma unroll
                for (int n = 0; n < 4; n++) {
                    asm volatile(
                        "mma.sync.aligned.m16n8k16.row.col.f32.f16.f16.f32 "
                        "{%0,%1,%2,%3}, {%4,%5,%6,%7}, {%8,%9}, {%0,%1,%2,%3};\n"
                        : "+f"(pacc[m][n][0]), "+f"(pacc[m][n][1]),
                          "+f"(pacc[m][n][2]), "+f"(pacc[m][n][3])
                        : "r"(a[m][0]), "r"(a[m][1]), "r"(a[m][2]), "r"(a[m][3]),
                          "r"(b[n][0]), "r"(b[n][1]));
                }
        }

        // ---- relu + fp16 -> Ps  (c0,c1 -> row gid; c2,c3 -> row gid+8)
#pragma unroll
        for (int m = 0; m < 2; m++) {
            int rbase = warpM * 32 + m * 16;
#pragma unroll
            for (int n = 0; n < 4; n++) {
                int col = warpJ * 32 + n * 8 + tig * 2;
                float v0 = fmaxf(pacc[m][n][0], 0.f), v1 = fmaxf(pacc[m][n][1], 0.f);
                float v2 = fmaxf(pacc[m][n][2], 0.f), v3 = fmaxf(pacc[m][n][3], 0.f);
                *reinterpret_cast<__half2*>(&Ps[rbase + gid    ][col]) = __floats2half2_rn(v0, v1);
                *reinterpret_cast<__half2*>(&Ps[rbase + gid + 8][col]) = __floats2half2_rn(v2, v3);
            }
        }
        __syncthreads();

        // ---- GEMM2: oacc += Ps @ W2s^T  (warp tile 32x64, K=64)
#pragma unroll
        for (int k0 = 0; k0 < 64; k0 += 16) {
            unsigned a[2][4], b[8][2];
#pragma unroll
            for (int m = 0; m < 2; m++)
                ldsm_x4(a[m], pBase + (unsigned)((m * 16 * LDSP + k0) * 2));
#pragma unroll
            for (int p = 0; p < 4; p++) {
                unsigned d[4];
                ldsm_x4(d, w2Base + (unsigned)((p * 16 * LDSP + k0) * 2));
                b[2 * p][0] = d[0]; b[2 * p][1] = d[1];
                b[2 * p + 1][0] = d[2]; b[2 * p + 1][1] = d[3];
            }
#pragma unroll
            for (int m = 0; m < 2; m++)
#pragma unroll
                for (int n = 0; n < 8; n++) {
                    asm volatile(
                        "mma.sync.aligned.m16n8k16.row.col.f32.f16.f16.f32 "
                        "{%0,%1,%2,%3}, {%4,%5,%6,%7}, {%8,%9}, {%0,%1,%2,%3};\n"
                        : "+f"(oacc[m][n][0]), "+f"(oacc[m][n][1]),
                          "+f"(oacc[m][n][2]), "+f"(oacc[m][n][3])
                        : "r"(a[m][0]), "r"(a[m][1]), "r"(a[m][2]), "r"(a[m][3]),
                          "r"(b[n][0]), "r"(b[n][1]));
                }
        }
        __syncthreads();   // before next chunk overwrites W1s/W2s/Ps
    }

    // ---- epilogue: C = GSCALE * oacc  (fp16)
#pragma unroll
    for (int m = 0; m < 2; m++) {
        int rbase = rowBase + warpM * 32 + m * 16;
#pragma unroll
        for (int n = 0; n < 8; n++) {
            int col = warpJ * 64 + n * 8 + tig * 2;
            float v0 = oacc[m][n][0] * GSCALE, v1 = oacc[m][n][1] * GSCALE;
            float v2 = oacc[m][n][2] * GSCALE, v3 = oacc[m][n][3] * GSCALE;
            int r0 = rbase + gid;
            int r1 = rbase + gid + 8;
            if (r0 < N)
                *reinterpret_cast<__half2*>(C + (size_t)r0 * 128 + col) = __floats2half2_rn(v0, v1);
            if (r1 < N)
                *reinterpret_cast<__half2*>(C + (size_t)r1 * 128 + col) = __floats2half2_rn(v2, v3);
        }
    }
}

// ---------------------------------------------------------------------------
// Sequence:
//   memset cnt; prep (ELL scatter + vectorized fp16 converts)
//   h1 = A@xh; h2 = A@h1
//   g' = 1024*relu(h2@W1^T)@W2^T   (fused, ldmatrix)
//   t' = A@g';  out = (A@t')/1024  (fp32)
// ---------------------------------------------------------------------------
extern "C" void kernel_launch(void* const* d_in, const int* in_sizes, int n_in,
                              void* d_out, int out_size) {
    const float* x    = (const float*)d_in[0];
    const int*   rows = (const int*)  d_in[1];
    const int*   cols = (const int*)  d_in[2];
    const float* vals = (const float*)d_in[3];
    const float* W1   = (const float*)d_in[4];
    const float* W2   = (const float*)d_in[5];
    float* out = (float*)d_out;

    const int nnz = in_sizes[1];
    const int N   = N_NODES;

    __half *xh, *ha, *hb, *w1h, *w2h;
    int *cnt;
    cudaGetSymbolAddress((void**)&xh,  g_xh);
    cudaGetSymbolAddress((void**)&ha,  g_ha);
    cudaGetSymbolAddress((void**)&hb,  g_hb);
    cudaGetSymbolAddress((void**)&w1h, g_w1h);
    cudaGetSymbolAddress((void**)&w2h, g_w2h);
    cudaGetSymbolAddress((void**)&cnt, g_cnt);

    const int BT = 256;
    const int spmmBlocks = (N * 32 + BT - 1) / BT;

    // fused smem: (128+64)*136 + (128+128)*72 halves = 89,088 B
    const int smemFused = (192 * LDSA + 256 * LDSP) * (int)sizeof(__half);
    cudaFuncSetAttribute(fused_mlp_kernel,
                         cudaFuncAttributeMaxDynamicSharedMemorySize, smemFused);

    // ---- ELL build + converts
    cudaMemsetAsync(cnt, 0, N * sizeof(int));
    {
        int p0 = N * 128 / 2, p1 = 256 * 128 / 2, p2 = 128 * 256 / 2;
        long long tot = (long long)nnz + p0 + p1 + p2;
        prep_kernel<<<(int)((tot + BT - 1) / BT), BT>>>(rows, cols, vals, nnz,
                                                        x, p0, W1, p1, W2, p2);
    }

    // ---- layer 1 propagates
    spmm_ell_kernel<true><<<spmmBlocks, BT>>>(xh, ha, 1.0f);   // h1
    spmm_ell_kernel<true><<<spmmBlocks, BT>>>(ha, hb, 1.0f);   // h2

    // ---- fused MLP: g' = 1024 * relu(h2@W1^T)@W2^T  -> ha
    fused_mlp_kernel<<<(N + 127) / 128, 256, smemFused>>>(hb, w1h, w2h, ha, N);

    // ---- layer 2 propagates
    spmm_ell_kernel<true ><<<spmmBlocks, BT>>>(ha, hb, 1.0f);        // t' = A@g'
    spmm_ell_kernel<false><<<spmmBlocks, BT>>>(hb, out, GSCALE_INV); // out = (A@t')/1024
}

// round 12
// speedup vs baseline: 2.8328x; 1.0500x over previous
#include <cuda_runtime.h>
#include <cuda_fp16.h>
#include <cuda_bf16.h>

#define N_NODES 100000
#define MAX_NNZ 3200000
#define ELL_CAP 128   // slots/row; Poisson(32) => P(deg>=128) ~ e^-88, never hit

// Exact power-of-2 scaling for post-W2 stages (keeps t' in fp16-normal range)
#define GSCALE     1024.0f
#define GSCALE_INV (1.0f / 1024.0f)

// ---------------- scratch (no cudaMalloc allowed) ----------------
__device__ __half g_xh [(size_t)N_NODES * 128];
__device__ __half g_ha [(size_t)N_NODES * 128];
__device__ __half g_hb [(size_t)N_NODES * 128];
__device__ __half g_w1h[256 * 128];
__device__ __half g_w2h[128 * 256];
__device__ int    g_cnt[N_NODES];
__device__ unsigned long long g_ell[(size_t)N_NODES * ELL_CAP]; // (col lo, val bits hi)

// ---------------------------------------------------------------------------
// Prep: ELL scatter + fp32->fp16 converts (vectorized, float2 -> half2).
// ---------------------------------------------------------------------------
__global__ void prep_kernel(const int* __restrict__ rows,
                            const int* __restrict__ cols,
                            const float* __restrict__ vals, int nnz,
                            const float* __restrict__ x,  int p0,   // pairs
                            const float* __restrict__ w1, int p1,
                            const float* __restrict__ w2, int p2) {
    int i = blockIdx.x * blockDim.x + threadIdx.x;
    if (i < nnz) {
        int r = rows[i];
        int pos = atomicAdd(&g_cnt[r], 1);
        if (pos < ELL_CAP) {
            unsigned vbits = __float_as_uint(vals[i]);
            g_ell[(size_t)r * ELL_CAP + pos] =
                (unsigned long long)(unsigned)cols[i]
              | ((unsigned long long)vbits << 32);
        }
        return;
    }
    i -= nnz;
    if (i < p0) {
        float2 f = reinterpret_cast<const float2*>(x)[i];
        reinterpret_cast<__half2*>(g_xh)[i] = __floats2half2_rn(f.x, f.y);
        return;
    }
    i -= p0;
    if (i < p1) {
        float2 f = reinterpret_cast<const float2*>(w1)[i];
        reinterpret_cast<__half2*>(g_w1h)[i] = __floats2half2_rn(f.x, f.y);
        return;
    }
    i -= p1;
    if (i < p2) {
        float2 f = reinterpret_cast<const float2*>(w2)[i];
        reinterpret_cast<__half2*>(g_w2h)[i] = __floats2half2_rn(f.x, f.y);
    }
}

// ---------------------------------------------------------------------------
// Gather SpMM (d=128): one warp per row, lane owns 4 features, fp32 accum.
// ---------------------------------------------------------------------------
__device__ __forceinline__ void acc_edge(const __half* __restrict__ h,
                                         const unsigned long long* __restrict__ ebase,
                                         int e, int lane, float4& acc) {
    uint2 p = __ldg(reinterpret_cast<const uint2*>(ebase + e));
    int   c = (int)p.x;
    float v = __uint_as_float(p.y);
    uint2 u = __ldg(reinterpret_cast<const uint2*>(h + (size_t)c * 128) + lane);
    __half2 p0 = *reinterpret_cast<__half2*>(&u.x);
    __half2 p1 = *reinterpret_cast<__half2*>(&u.y);
    float2 f0 = __half22float2(p0);
    float2 f1 = __half22float2(p1);
    acc.x = fmaf(v, f0.x, acc.x); acc.y = fmaf(v, f0.y, acc.y);
    acc.z = fmaf(v, f1.x, acc.z); acc.w = fmaf(v, f1.y, acc.w);
}

template <bool OUT_HALF>
__global__ void __launch_bounds__(256)
spmm_ell_kernel(const __half* __restrict__ h, void* __restrict__ outv, float oscale) {
    int r = (blockIdx.x * blockDim.x + threadIdx.x) >> 5;
    if (r >= N_NODES) return;
    int lane = threadIdx.x & 31;

    int cnt = __ldg(&g_cnt[r]);
    if (cnt > ELL_CAP) cnt = ELL_CAP;
    const unsigned long long* ebase = g_ell + (size_t)r * ELL_CAP;

    float4 acc = make_float4(0.f, 0.f, 0.f, 0.f);
    int e = 0;
    for (; e + 3 < cnt; e += 4) {
        acc_edge(h, ebase, e,     lane, acc);
        acc_edge(h, ebase, e + 1, lane, acc);
        acc_edge(h, ebase, e + 2, lane, acc);
        acc_edge(h, ebase, e + 3, lane, acc);
    }
    for (; e < cnt; e++) acc_edge(h, ebase, e, lane, acc);

    acc.x *= oscale; acc.y *= oscale; acc.z *= oscale; acc.w *= oscale;

    if (OUT_HALF) {
        __half2 o0 = __floats2half2_rn(acc.x, acc.y);
        __half2 o1 = __floats2half2_rn(acc.z, acc.w);
        uint2 u;
        u.x = *reinterpret_cast<unsigned*>(&o0);
        u.y = *reinterpret_cast<unsigned*>(&o1);
        *(reinterpret_cast<uint2*>((__half*)outv + (size_t)r * 128) + lane) = u;
    } else {
        *(reinterpret_cast<float4*>((float*)outv + (size_t)r * 128) + lane) = acc;
    }
}

// ---------------------------------------------------------------------------
// asm helpers
// ---------------------------------------------------------------------------
__device__ __forceinline__ void ldsm_x4(unsigned* d, unsigned addr) {
    asm volatile("ldmatrix.sync.aligned.m8n8.x4.shared.b16 {%0,%1,%2,%3}, [%4];"
                 : "=r"(d[0]), "=r"(d[1]), "=r"(d[2]), "=r"(d[3]) : "r"(addr));
}
__device__ __forceinline__ void cp16(unsigned dst, const void* src) {
    asm volatile("cp.async.cg.shared.global [%0], [%1], 16;" :: "r"(dst), "l"(src));
}
__device__ __forceinline__ void cp_commit() {
    asm volatile("cp.async.commit_group;");
}
template <int NG>
__device__ __forceinline__ void cp_wait() {
    asm volatile("cp.async.wait_group %0;" :: "n"(NG));
}
__device__ __forceinline__ void mma16816(float* c, const unsigned* a, unsigned b0, unsigned b1) {
    asm volatile(
        "mma.sync.aligned.m16n8k16.row.col.f32.f16.f16.f32 "
        "{%0,%1,%2,%3}, {%4,%5,%6,%7}, {%8,%9}, {%0,%1,%2,%3};\n"
        : "+f"(c[0]), "+f"(c[1]), "+f"(c[2]), "+f"(c[3])
        : "r"(a[0]), "r"(a[1]), "r"(a[2]), "r"(a[3]), "r"(b0), "r"(b1));
}

// ---------------------------------------------------------------------------
// Fused MLP: C = GSCALE * ( relu(A @ W1^T) @ W2^T ),  [N,128], fp16.
// Register-resident fusion: each warp owns 16 rows and computes ALL chunk
// features in GEMM1, so GEMM2's A-fragments are an in-register repack of
// GEMM1's accumulators (relu applied during the pack). No P smem, no
// mid-chunk barriers. W1/W2 chunks double-buffered via cp.async.
// smem/CTA = 106,496 B; 2 CTAs/SM.
// ---------------------------------------------------------------------------
#define LDSA 136
#define LDSP 72
#define SM_AS   0                              // 128 x LDSA
#define SM_W1(s) (128 * LDSA + (s) * 64 * LDSA)  // 2 x 64 x LDSA
#define SM_W2(s) (128 * LDSA + 2 * 64 * LDSA + (s) * 128 * LDSP)  // 2 x 128 x LDSP
#define SM_TOTAL (128 * LDSA + 2 * 64 * LDSA + 2 * 128 * LDSP)    // 53,248 halves

__global__ void __launch_bounds__(256, 2)
fused_mlp_kernel(const __half* __restrict__ A,
                 const __half* __restrict__ W1,
                 const __half* __restrict__ W2,
                 __half* __restrict__ C, int N) {
    extern __shared__ __half sm[];

    const int tid  = threadIdx.x;
    const int lane = tid & 31;
    const int wid  = tid >> 5;          // 0..7, warp owns rows wid*16..+16
    const int gid = lane >> 2;
    const int tig = lane & 3;
    const int rowBase = blockIdx.x * 128;

    // ldmatrix lane-address components (validated by R11's passing run):
    const int lane15 = lane & 15;
    const int laneK8 = (lane & 16) ? 8 : 0;
    const int laneJ  = ((lane & 16) ? 8 : 0) + (lane & 7);
    const int laneBK = (lane & 8) ? 8 : 0;

    const unsigned smBase = (unsigned)__cvta_generic_to_shared(sm);

    // ---- prologue: A tile (cp.async; OOB rows zero-filled) + W chunk 0, 1
    for (int i = tid; i < 128 * 16; i += 256) {
        int row = i >> 4, seg = (i & 15) * 8;
        unsigned dst = smBase + (unsigned)((SM_AS + row * LDSA + seg) * 2);
        int arow = rowBase + row;
        if (arow < N) {
            cp16(dst, A + (size_t)arow * 128 + seg);
        } else {
            uint4 z = make_uint4(0, 0, 0, 0);
            *reinterpret_cast<uint4*>(sm + SM_AS + row * LDSA + seg) = z;
        }
    }
    // W chunk loader: W1 rows kc*64..+64 (all 128 k); W2 all 128 rows, k kc*64..+64
    auto loadW = [&](int kc, int s) {
        for (int i = tid; i < 64 * 16; i += 256) {
            int row = i >> 4, seg = (i & 15) * 8;
            cp16(smBase + (unsigned)((SM_W1(s) + row * LDSA + seg) * 2),
                 W1 + (size_t)(kc * 64 + row) * 128 + seg);
        }
        for (int i = tid; i < 128 * 8; i += 256) {
            int row = i >> 3, seg = (i & 7) * 8;
            cp16(smBase + (unsigned)((SM_W2(s) + row * LDSP + seg) * 2),
                 W2 + (size_t)row * 256 + kc * 64 + seg);
        }
    };
    loadW(0, 0); cp_commit();   // group G0 (includes A)
    loadW(1, 1); cp_commit();   // group G1

    const unsigned aBase = smBase + (unsigned)((SM_AS + (wid * 16 + lane15) * LDSA + laneK8) * 2);

    float oacc[16][4];
#pragma unroll
    for (int n = 0; n < 16; n++)
#pragma unroll
        for (int q = 0; q < 4; q++) oacc[n][q] = 0.f;

#pragma unroll
    for (int kc = 0; kc < 4; kc++) {
        const int s = kc & 1;
        if (kc >= 1 && kc < 3) { loadW(kc + 1, (kc + 1) & 1); cp_commit(); }
        if (kc < 3) cp_wait<1>(); else cp_wait<0>();
        __syncthreads();

        const unsigned w1Base = smBase + (unsigned)((SM_W1(s) + laneJ * LDSA + laneBK) * 2);
        const unsigned w2Base = smBase + (unsigned)((SM_W2(s) + laneJ * LDSP + laneBK) * 2);

        unsigned ah[4][4];   // GEMM2 A-fragments: ah[q] = features q*16..+16

        // ---- GEMM1 in two 32-feature halves (keeps register peak low)
#pragma unroll
        for (int hh = 0; hh < 2; hh++) {
            float pacc[4][4];
#pragma unroll
            for (int n = 0; n < 4; n++)
#pragma unroll
                for (int q = 0; q < 4; q++) pacc[n][q] = 0.f;

#pragma unroll
            for (int k0 = 0; k0 < 128; k0 += 16) {
                unsigned a[4];
                ldsm_x4(a, aBase + (unsigned)(k0 * 2));
                unsigned b[4][2];
#pragma unroll
                for (int p = 0; p < 2; p++) {
                    unsigned d[4];
                    ldsm_x4(d, w1Base + (unsigned)(((hh * 32 + p * 16) * LDSA + k0) * 2));
                    b[2 * p][0] = d[0]; b[2 * p][1] = d[1];
                    b[2 * p + 1][0] = d[2]; b[2 * p + 1][1] = d[3];
                }
#pragma unroll
                for (int n = 0; n < 4; n++)
                    mma16816(pacc[n], a, b[n][0], b[n][1]);
            }

            // relu + pack into GEMM2 A-fragments (pure register repack):
            // pacc[2q](c0,c1)->(gid, f=16q+tig*2) ; (c2,c3)->(gid+8)
            // pacc[2q+1] is features +8 -> a2/a3 slots.
#pragma unroll
            for (int qq = 0; qq < 2; qq++) {
                int q = hh * 2 + qq;
                __half2 t0 = __floats2half2_rn(fmaxf(pacc[2 * qq][0], 0.f), fmaxf(pacc[2 * qq][1], 0.f));
                __half2 t1 = __floats2half2_rn(fmaxf(pacc[2 * qq][2], 0.f), fmaxf(pacc[2 * qq][3], 0.f));
                __half2 t2 = __floats2half2_rn(fmaxf(pacc[2 * qq + 1][0], 0.f), fmaxf(pacc[2 * qq + 1][1], 0.f));
                __half2 t3 = __floats2half2_rn(fmaxf(pacc[2 * qq + 1][2], 0.f), fmaxf(pacc[2 * qq + 1][3], 0.f));
                ah[q][0] = *reinterpret_cast<unsigned*>(&t0);
                ah[q][1] = *reinterpret_cast<unsigned*>(&t1);
                ah[q][2] = *reinterpret_cast<unsigned*>(&t2);
                ah[q][3] = *reinterpret_cast<unsigned*>(&t3);
            }
        }

        // ---- GEMM2: oacc += P @ W2chunk^T   (k = 64 chunk features)
#pragma unroll
        for (int q = 0; q < 4; q++) {
#pragma unroll
            for (int p = 0; p < 8; p++) {
                unsigned d[4];
                ldsm_x4(d, w2Base + (unsigned)((p * 16 * LDSP + q * 16) * 2));
                mma16816(oacc[2 * p],     ah[q], d[0], d[1]);
                mma16816(oacc[2 * p + 1], ah[q], d[2], d[3]);
            }
        }
        __syncthreads();   // all warps done with buf s before it's reloaded
    }

    // ---- epilogue: C = GSCALE * oacc (fp16); oacc[n] -> cols n*8 + tig*2
    int r0 = rowBase + wid * 16 + gid;
    int r1 = r0 + 8;
#pragma unroll
    for (int n = 0; n < 16; n++) {
        int col = n * 8 + tig * 2;
        if (r0 < N) {
            __half2 p = __floats2half2_rn(oacc[n][0] * GSCALE, oacc[n][1] * GSCALE);
            *reinterpret_cast<__half2*>(C + (size_t)r0 * 128 + col) = p;
        }
        if (r1 < N) {
            __half2 p = __floats2half2_rn(oacc[n][2] * GSCALE, oacc[n][3] * GSCALE);
            *reinterpret_cast<__half2*>(C + (size_t)r1 * 128 + col) = p;
        }
    }
}

// ---------------------------------------------------------------------------
// Sequence:
//   memset cnt; prep (ELL scatter + vectorized fp16 converts)
//   h1 = A@xh; h2 = A@h1
//   g' = 1024*relu(h2@W1^T)@W2^T   (register-fused, cp.async pipelined)
//   t' = A@g';  out = (A@t')/1024  (fp32)
// ---------------------------------------------------------------------------
extern "C" void kernel_launch(void* const* d_in, const int* in_sizes, int n_in,
                              void* d_out, int out_size) {
    const float* x    = (const float*)d_in[0];
    const int*   rows = (const int*)  d_in[1];
    const int*   cols = (const int*)  d_in[2];
    const float* vals = (const float*)d_in[3];
    const float* W1   = (const float*)d_in[4];
    const float* W2   = (const float*)d_in[5];
    float* out = (float*)d_out;

    const int nnz = in_sizes[1];
    const int N   = N_NODES;

    __half *xh, *ha, *hb, *w1h, *w2h;
    int *cnt;
    cudaGetSymbolAddress((void**)&xh,  g_xh);
    cudaGetSymbolAddress((void**)&ha,  g_ha);
    cudaGetSymbolAddress((void**)&hb,  g_hb);
    cudaGetSymbolAddress((void**)&w1h, g_w1h);
    cudaGetSymbolAddress((void**)&w2h, g_w2h);
    cudaGetSymbolAddress((void**)&cnt, g_cnt);

    const int BT = 256;
    const int spmmBlocks = (N * 32 + BT - 1) / BT;

    const int smemFused = SM_TOTAL * (int)sizeof(__half);   // 106,496 B
    cudaFuncSetAttribute(fused_mlp_kernel,
                         cudaFuncAttributeMaxDynamicSharedMemorySize, smemFused);

    // ---- ELL build + converts
    cudaMemsetAsync(cnt, 0, N * sizeof(int));
    {
        int p0 = N * 128 / 2, p1 = 256 * 128 / 2, p2 = 128 * 256 / 2;
        long long tot = (long long)nnz + p0 + p1 + p2;
        prep_kernel<<<(int)((tot + BT - 1) / BT), BT>>>(rows, cols, vals, nnz,
                                                        x, p0, W1, p1, W2, p2);
    }

    // ---- layer 1 propagates
    spmm_ell_kernel<true><<<spmmBlocks, BT>>>(xh, ha, 1.0f);   // h1
    spmm_ell_kernel<true><<<spmmBlocks, BT>>>(ha, hb, 1.0f);   // h2

    // ---- fused MLP: g' = 1024 * relu(h2@W1^T)@W2^T  -> ha
    fused_mlp_kernel<<<(N + 127) / 128, 256, smemFused>>>(hb, w1h, w2h, ha, N);

    // ---- layer 2 propagates
    spmm_ell_kernel<true ><<<spmmBlocks, BT>>>(ha, hb, 1.0f);        // t' = A@g'
    spmm_ell_kernel<false><<<spmmBlocks, BT>>>(hb, out, GSCALE_INV); // out = (A@t')/1024
}